// round 5
// baseline (speedup 1.0000x reference)
#include <cuda_runtime.h>
#include <cstdint>

// Problem constants
#define BDIM 64
#define ICC  128
#define OCC  128
#define OD   1024          // out_dim; L = 2*OD
#define KC   16            // ic chunk held in smem
#define DT   2             // d's per block
#define OCT  64            // o's per block

using ull = unsigned long long;

// Packed 2xFP32 FMA: d.lo += a.lo*b.lo ; d.hi += a.hi*b.hi  (FFMA2, sm_100+)
#define FMA_F32X2(d_, a_, b_) \
  asm("fma.rn.f32x2 %0, %1, %2, %0;" : "+l"(d_) : "l"(a_), "l"(b_))

__global__ void __launch_bounds__(256)
nolc1d_kernel(const float2* __restrict__ X2,   // x viewed as (B, IC, OD) float2
              const float2* __restrict__ W2,   // w viewed as (OC, IC, OD) float2
              float* __restrict__ out)         // (B, OC, OD)
{
    __shared__ __align__(16) float2 Xs[KC][DT][BDIM];  // 16 KB
    __shared__ __align__(16) float2 Ws[KC][DT][OCT];   // 16 KB

    const int tid = threadIdx.x;
    const int d0  = blockIdx.x * DT;       // 0..1022 step 2
    const int oc0 = blockIdx.y * OCT;      // 0 or 64

    // compute-side decomposition: dg selects the d slice, 128 threads per slice
    const int dg = tid >> 7;               // 0..1
    const int t  = tid & 127;
    const int ty = t >> 4;                 // 0..7  -> 8 b-rows each
    const int tx = t & 15;                 // 0..15 -> 4 o-cols each
    const int b0 = ty * 8;
    const int ol = tx * 4;

    // loader decomposition: row r = tid + i*256 -> k = lk + 4*i, col = lc
    const int lk = tid >> 6;               // 0..3
    const int lc = tid & 63;               // b (for X) / local o (for W)

    const float2* xbase = X2 + (size_t)lc * (ICC * OD) + d0;
    const float2* wbase = W2 + (size_t)(oc0 + lc) * (ICC * OD) + d0;

    ull acc[8][4];
    #pragma unroll
    for (int i = 0; i < 8; ++i)
        #pragma unroll
        for (int j = 0; j < 4; ++j)
            acc[i][j] = 0ull;   // two packed +0.0f

    for (int kc = 0; kc < ICC; kc += KC) {
        // ---- global -> smem: each thread loads 4 rows of X and 4 of W,
        // each row = float4 = the (d0, d0+1) pair-of-pairs for one (col, ic).
        #pragma unroll
        for (int i = 0; i < 4; ++i) {
            const int k = lk + i * 4;
            float4 gx = *reinterpret_cast<const float4*>(xbase + (size_t)(kc + k) * OD);
            Xs[k][0][lc] = make_float2(gx.x, gx.y);
            Xs[k][1][lc] = make_float2(gx.z, gx.w);
            float4 gw = *reinterpret_cast<const float4*>(wbase + (size_t)(kc + k) * OD);
            Ws[k][0][lc] = make_float2(gw.x, gw.y);
            Ws[k][1][lc] = make_float2(gw.z, gw.w);
        }
        __syncthreads();

        // ---- compute: 16 k-steps, 8x4 packed outer product per step
        #pragma unroll
        for (int k = 0; k < KC; ++k) {
            ull xv[8], wv[4];
            const ulonglong2* xp =
                reinterpret_cast<const ulonglong2*>(&Xs[k][dg][b0]);
            ulonglong2 a0 = xp[0], a1 = xp[1], a2 = xp[2], a3 = xp[3];
            xv[0] = a0.x; xv[1] = a0.y; xv[2] = a1.x; xv[3] = a1.y;
            xv[4] = a2.x; xv[5] = a2.y; xv[6] = a3.x; xv[7] = a3.y;
            const ulonglong2* wp =
                reinterpret_cast<const ulonglong2*>(&Ws[k][dg][ol]);
            ulonglong2 w0 = wp[0], w1 = wp[1];
            wv[0] = w0.x; wv[1] = w0.y; wv[2] = w1.x; wv[3] = w1.y;

            #pragma unroll
            for (int bb = 0; bb < 8; ++bb)
                #pragma unroll
                for (int oo = 0; oo < 4; ++oo)
                    FMA_F32X2(acc[bb][oo], xv[bb], wv[oo]);
        }
        __syncthreads();
    }

    // ---- epilogue: out = (lo + hi) / sqrt(IC)
    const float scale = 0.08838834764831843f;  // 1/sqrt(128)
    const int dcol = d0 + dg;
    #pragma unroll
    for (int bb = 0; bb < 8; ++bb) {
        const int b = b0 + bb;
        #pragma unroll
        for (int oo = 0; oo < 4; ++oo) {
            const int o = oc0 + ol + oo;
            float2 v = *reinterpret_cast<float2*>(&acc[bb][oo]);
            out[((size_t)b * OCC + o) * OD + dcol] = (v.x + v.y) * scale;
        }
    }
}

extern "C" void kernel_launch(void* const* d_in, const int* in_sizes, int n_in,
                              void* d_out, int out_size)
{
    // x: (64,128,2048) = 16,777,216 floats ; weight: (128,128,2048) = 33,554,432
    const void* xa = d_in[0];
    const void* wa = d_in[1];
    if (n_in >= 2 && in_sizes[0] == OCC * ICC * 2 * OD &&
        in_sizes[1] == BDIM * ICC * 2 * OD) {
        const void* tmp = xa; xa = wa; wa = tmp;  // defensive: order swapped
    }
    const float2* x = reinterpret_cast<const float2*>(xa);
    const float2* w = reinterpret_cast<const float2*>(wa);
    float* out = reinterpret_cast<float*>(d_out);

    dim3 grid(OD / DT, OCC / OCT);   // (512, 2)
    nolc1d_kernel<<<grid, 256>>>(x, w, out);
}

// round 6
// speedup vs baseline: 1.1463x; 1.1463x over previous
#include <cuda_runtime.h>
#include <cstdint>

// Problem constants
#define BDIM 64
#define ICC  128
#define OCC  128
#define OD   1024          // out_dim; L = 2*OD
#define KC   16            // ic chunk held in smem
#define DT   2             // d's per block
#define OCT  64            // o's per block

using ull = unsigned long long;

// Packed 2xFP32 FMA: d.lo += a.lo*b.lo ; d.hi += a.hi*b.hi  (FFMA2, sm_100+)
#define FMA_F32X2(d_, a_, b_) \
  asm("fma.rn.f32x2 %0, %1, %2, %0;" : "+l"(d_) : "l"(a_), "l"(b_))

__global__ void __launch_bounds__(256, 2)
nolc1d_kernel(const float2* __restrict__ X2,   // x viewed as (B, IC, OD) float2
              const float2* __restrict__ W2,   // w viewed as (OC, IC, OD) float2
              float* __restrict__ out)         // (B, OC, OD)
{
    __shared__ __align__(16) float2 Xs[KC][DT][BDIM];  // 16 KB
    __shared__ __align__(16) float2 Ws[KC][DT][OCT];   // 16 KB

    const int tid = threadIdx.x;
    const int d0  = blockIdx.x * DT;       // 0..1022 step 2
    const int oc0 = blockIdx.y * OCT;      // 0 or 64

    // compute-side decomposition: dg selects the d slice, 128 threads per slice
    const int dg = tid >> 7;               // 0..1
    const int t  = tid & 127;
    const int ty = t >> 4;                 // 0..7  -> 8 b-rows each
    const int tx = t & 15;                 // 0..15 -> 4 o-cols each
    const int b0 = ty * 8;
    const int ol = tx * 4;

    // loader decomposition: row r = tid + i*256 -> k = lk + 4*i, col = lc
    const int lk = tid >> 6;               // 0..3
    const int lc = tid & 63;               // b (for X) / local o (for W)

    const float2* xbase = X2 + (size_t)lc * (ICC * OD) + d0;
    const float2* wbase = W2 + (size_t)(oc0 + lc) * (ICC * OD) + d0;

    ull acc[8][4];
    #pragma unroll
    for (int i = 0; i < 8; ++i)
        #pragma unroll
        for (int j = 0; j < 4; ++j)
            acc[i][j] = 0ull;   // two packed +0.0f

    for (int kc = 0; kc < ICC; kc += KC) {
        // ---- global -> smem: each thread loads 4 rows of X and 4 of W,
        // each row = float4 = the (d0, d0+1) pair-of-pairs for one (col, ic).
        #pragma unroll
        for (int i = 0; i < 4; ++i) {
            const int k = lk + i * 4;
            float4 gx = *reinterpret_cast<const float4*>(xbase + (size_t)(kc + k) * OD);
            Xs[k][0][lc] = make_float2(gx.x, gx.y);
            Xs[k][1][lc] = make_float2(gx.z, gx.w);
            float4 gw = *reinterpret_cast<const float4*>(wbase + (size_t)(kc + k) * OD);
            Ws[k][0][lc] = make_float2(gw.x, gw.y);
            Ws[k][1][lc] = make_float2(gw.z, gw.w);
        }
        __syncthreads();

        // ---- compute: 16 k-steps; per step, hold 4 w-frags and stream
        // x-frags 4 at a time (keeps live frag regs at 16 -> 2 CTAs/SM).
        #pragma unroll
        for (int k = 0; k < KC; ++k) {
            ull wv[4];
            {
                const ulonglong2* wp =
                    reinterpret_cast<const ulonglong2*>(&Ws[k][dg][ol]);
                ulonglong2 w0 = wp[0], w1 = wp[1];
                wv[0] = w0.x; wv[1] = w0.y; wv[2] = w1.x; wv[3] = w1.y;
            }
            const ulonglong2* xp =
                reinterpret_cast<const ulonglong2*>(&Xs[k][dg][b0]);

            #pragma unroll
            for (int h = 0; h < 2; ++h) {
                ull xv[4];
                ulonglong2 a0 = xp[2 * h + 0], a1 = xp[2 * h + 1];
                xv[0] = a0.x; xv[1] = a0.y; xv[2] = a1.x; xv[3] = a1.y;

                #pragma unroll
                for (int bb = 0; bb < 4; ++bb)
                    #pragma unroll
                    for (int oo = 0; oo < 4; ++oo)
                        FMA_F32X2(acc[4 * h + bb][oo], xv[bb], wv[oo]);
            }
        }
        __syncthreads();
    }

    // ---- epilogue: out = (lo + hi) / sqrt(IC)
    const float scale = 0.08838834764831843f;  // 1/sqrt(128)
    const int dcol = d0 + dg;
    #pragma unroll
    for (int bb = 0; bb < 8; ++bb) {
        const int b = b0 + bb;
        #pragma unroll
        for (int oo = 0; oo < 4; ++oo) {
            const int o = oc0 + ol + oo;
            float2 v = *reinterpret_cast<float2*>(&acc[bb][oo]);
            out[((size_t)b * OCC + o) * OD + dcol] = (v.x + v.y) * scale;
        }
    }
}

extern "C" void kernel_launch(void* const* d_in, const int* in_sizes, int n_in,
                              void* d_out, int out_size)
{
    // x: (64,128,2048) = 16,777,216 floats ; weight: (128,128,2048) = 33,554,432
    const void* xa = d_in[0];
    const void* wa = d_in[1];
    if (n_in >= 2 && in_sizes[0] == OCC * ICC * 2 * OD &&
        in_sizes[1] == BDIM * ICC * 2 * OD) {
        const void* tmp = xa; xa = wa; wa = tmp;  // defensive: order swapped
    }
    const float2* x = reinterpret_cast<const float2*>(xa);
    const float2* w = reinterpret_cast<const float2*>(wa);
    float* out = reinterpret_cast<float*>(d_out);

    dim3 grid(OD / DT, OCC / OCT);   // (512, 2)
    nolc1d_kernel<<<grid, 256>>>(x, w, out);
}